// round 1
// baseline (speedup 1.0000x reference)
#include <cuda_runtime.h>
#include <math.h>

// Hyp-MLR: N=4096, C=256, D=128, CURV=1
// out[n,c] = 2*||a_c|| * asinh( dot * lam ) where everything reduces to
// scalars from x.p, x.a, x.x, p.p, a.a, p.a  (see derivation in analysis).

#define N_TOT 4096
#define C_TOT 256
#define D_TOT 128
#define BN 64
#define BC 64
#define KT 32
#define PAD 4   // row stride 68 floats: float4 compute loads stay 16B-aligned

__global__ __launch_bounds__(256) void hyp_mlr_kernel(
    const float* __restrict__ X,   // (N, D) output_before
    const float* __restrict__ A,   // (C, D) a_mlr
    const float* __restrict__ P,   // (C, D) p_mlr
    float* __restrict__ out)       // (N, C)
{
    __shared__ float Xs[KT][BN + PAD];
    __shared__ float Ps[KT][BC + PAD];
    __shared__ float As[KT][BC + PAD];

    const int tid = threadIdx.x;
    const int tx  = tid & 15;   // c dim (16 threads)
    const int ty  = tid >> 4;   // n dim (16 threads)
    const int n0  = blockIdx.y * BN;
    const int c0  = blockIdx.x * BC;

    float acc_xp[4][4] = {};
    float acc_xa[4][4] = {};
    float x2[4]  = {};
    float p2[4]  = {};
    float na2[4] = {};
    float pa[4]  = {};

    for (int k0 = 0; k0 < D_TOT; k0 += KT) {
        // Cooperative tile load: 64 rows x 32 k per array, coalesced on k.
        #pragma unroll
        for (int r = 0; r < 8; r++) {
            int idx = tid + r * 256;
            int kk  = idx & 31;
            int row = idx >> 5;           // 0..63
            Xs[kk][row] = X[(n0 + row) * D_TOT + k0 + kk];
            Ps[kk][row] = P[(c0 + row) * D_TOT + k0 + kk];
            As[kk][row] = A[(c0 + row) * D_TOT + k0 + kk];
        }
        __syncthreads();

        #pragma unroll
        for (int k = 0; k < KT; k++) {
            float4 xv = *(const float4*)&Xs[k][ty * 4];
            float4 pv = *(const float4*)&Ps[k][tx * 4];
            float4 av = *(const float4*)&As[k][tx * 4];
            float xr[4] = {xv.x, xv.y, xv.z, xv.w};
            float pr[4] = {pv.x, pv.y, pv.z, pv.w};
            float ar[4] = {av.x, av.y, av.z, av.w};

            #pragma unroll
            for (int i = 0; i < 4; i++) x2[i] = fmaf(xr[i], xr[i], x2[i]);
            #pragma unroll
            for (int j = 0; j < 4; j++) {
                p2[j]  = fmaf(pr[j], pr[j], p2[j]);
                na2[j] = fmaf(ar[j], ar[j], na2[j]);
                pa[j]  = fmaf(pr[j], ar[j], pa[j]);
            }
            #pragma unroll
            for (int i = 0; i < 4; i++)
                #pragma unroll
                for (int j = 0; j < 4; j++) {
                    acc_xp[i][j] = fmaf(xr[i], pr[j], acc_xp[i][j]);
                    acc_xa[i][j] = fmaf(xr[i], ar[j], acc_xa[i][j]);
                }
        }
        __syncthreads();
    }

    // Epilogue: per-(n,c) scalar math + asinh, vectorized store.
    #pragma unroll
    for (int i = 0; i < 4; i++) {
        const int n = n0 + ty * 4 + i;
        float res[4];
        #pragma unroll
        for (int j = 0; j < 4; j++) {
            float xy    = -acc_xp[i][j];                 // mp . x
            float alpha = 1.0f + 2.0f * xy + x2[i];
            float beta  = 1.0f - p2[j];
            float den   = 1.0f + 2.0f * xy + p2[j] * x2[i];
            float inv_den = 1.0f / den;
            float r2 = (alpha * alpha * p2[j]
                        + 2.0f * alpha * beta * xy
                        + beta * beta * x2[i]) * inv_den * inv_den;
            float lam = 2.0f / (1.0f - r2);
            float na  = sqrtf(na2[j]);
            float inv_na = 1.0f / fmaxf(na, 1e-12f);
            float dot = (beta * acc_xa[i][j] - alpha * pa[j]) * inv_den * inv_na;
            res[j] = 2.0f * na * asinhf(dot * lam);
        }
        float4 o = {res[0], res[1], res[2], res[3]};
        *(float4*)&out[(size_t)n * C_TOT + c0 + tx * 4] = o;
    }
}

extern "C" void kernel_launch(void* const* d_in, const int* in_sizes, int n_in,
                              void* d_out, int out_size) {
    const float* X = (const float*)d_in[0];   // output_before (N, D)
    const float* A = (const float*)d_in[1];   // a_mlr (C, D)
    const float* P = (const float*)d_in[2];   // p_mlr (C, D)
    float* out = (float*)d_out;               // (N, C)

    dim3 grid(C_TOT / BC, N_TOT / BN);        // (4, 64) = 256 blocks
    hyp_mlr_kernel<<<grid, 256>>>(X, A, P, out);
}